// round 14
// baseline (speedup 1.0000x reference)
#include <cuda_runtime.h>
#include <cuda_bf16.h>
#include <math.h>

// ---------------------------------------------------------------------------
// Problem constants
// ---------------------------------------------------------------------------
#define BATCH     2048
#define SDIM      64
#define ADIM      16
#define HID       256
#define TDIM      32
#define TSTEPS    100
#define CAT       112            // ADIM + TDIM + SDIM
#define RPC       16             // rows per CTA
#define NRP       8              // row-pairs per CTA
#define NCTA      (BATCH / RPC)  // 128
#define NTHR      512            // 64 cg x 2 row-halves x 4 k-splits
#define GSTR      18             // ull per 2-col group (16 data + 2 pad)

typedef unsigned long long ull;

// padded layout: value (col c, row-pair rp) at (c>>1)*GSTR + (c&1)*8 + rp
__device__ __forceinline__ int lay(int c, int rp) {
    return (c >> 1) * GSTR + (c & 1) * 8 + rp;
}

// ---------------------------------------------------------------------------
// Precomputed tables
// ---------------------------------------------------------------------------
__device__ float g_temb[TSTEPS * TDIM];
__device__ float g_srac[TSTEPS];
__device__ float g_sracm1[TSTEPS];
__device__ float g_c1[TSTEPS];
__device__ float g_c2[TSTEPS];
__device__ float g_sigma[TSTEPS];

// duplicated weights: Wd[k*cols + c] = {w, w}  (kills all pack-MOVs in the
// mainloop; L2 measured at only 13-16% so 2x weight bytes is safe)
__device__ __align__(16) ull g_W1d[CAT * HID];   // 229 KB
__device__ __align__(16) ull g_W2d[HID * HID];   // 512 KB
__device__ __align__(16) ull g_W3d[HID * HID];   // 512 KB
__device__ __align__(16) ull g_W4d[HID * ADIM];  //  32 KB

// ---------------------------------------------------------------------------
// f32x2 helpers
// ---------------------------------------------------------------------------
__device__ __forceinline__ ull pack2(float lo, float hi) {
    ull r; asm("mov.b64 %0, {%1, %2};" : "=l"(r) : "f"(lo), "f"(hi)); return r;
}
__device__ __forceinline__ void unpack2(ull v, float& lo, float& hi) {
    asm("mov.b64 {%0, %1}, %2;" : "=f"(lo), "=f"(hi) : "l"(v));
}
__device__ __forceinline__ void fma2(ull& d, ull a, ull b) {
    asm("fma.rn.f32x2 %0, %1, %2, %0;" : "+l"(d) : "l"(a), "l"(b));
}
__device__ __forceinline__ ull add2(ull a, ull b) {
    ull r; asm("add.rn.f32x2 %0, %1, %2;" : "=l"(r) : "l"(a), "l"(b)); return r;
}

// ---------------------------------------------------------------------------
// Fast exact-algebra mish: tanh(softplus(x)) = v/(v+2), v = u^2+2u, u = e^x
// ---------------------------------------------------------------------------
__device__ __forceinline__ float mishf(float x) {
    const float LOG2E = 1.4426950408889634f;
    float xc = fminf(x, 40.0f);
    float u;
    asm("ex2.approx.f32 %0, %1;" : "=f"(u) : "f"(xc * LOG2E));
    float v = fmaf(u, u, u + u);
    float r;
    asm("rcp.approx.f32 %0, %1;" : "=f"(r) : "f"(v + 2.0f));
    return x * v * r;
}

// ---------------------------------------------------------------------------
// Setup: build duplicated weight tables (once per launch, deterministic)
// ---------------------------------------------------------------------------
__global__ void setup_dup_kernel(const float* __restrict__ W1,
                                 const float* __restrict__ W2,
                                 const float* __restrict__ W3,
                                 const float* __restrict__ W4)
{
    int idx = blockIdx.x * blockDim.x + threadIdx.x;
    const int N1 = CAT * HID, N2 = HID * HID, N4 = HID * ADIM;
    if (idx < N1) { float w = W1[idx]; g_W1d[idx] = pack2(w, w); }
    if (idx < N2) { float w = W2[idx]; g_W2d[idx] = pack2(w, w); }
    if (idx < N2) { float w = W3[idx]; g_W3d[idx] = pack2(w, w); }
    if (idx < N4) { float w = W4[idx]; g_W4d[idx] = pack2(w, w); }
}

// ---------------------------------------------------------------------------
// Prolog: VP schedule in f64 + per-timestep time-MLP (batch-invariant).
// ---------------------------------------------------------------------------
__global__ void __launch_bounds__(256) prolog_kernel(
    const float* __restrict__ tW1, const float* __restrict__ tb1,
    const float* __restrict__ tW2, const float* __restrict__ tb2)
{
    const int tid = threadIdx.x;
    const int i   = blockIdx.x;

    if (i == 0 && tid == 0) {
        const double T = (double)TSTEPS, bmax = 10.0, bmin = 0.1;
        double ac = 1.0;
        for (int idx = 0; idx < TSTEPS; ++idx) {
            double t      = (double)(idx + 1);
            double alpha  = exp(-bmin / T - 0.5 * (bmax - bmin) * (2.0 * t - 1.0) / (T * T));
            double beta   = 1.0 - alpha;
            double acp    = ac;
            ac            = ac * alpha;
            g_srac[idx]   = (float)sqrt(1.0 / ac);
            g_sracm1[idx] = (float)sqrt(1.0 / ac - 1.0);
            g_c1[idx]     = (float)(beta * sqrt(acp) / (1.0 - ac));
            g_c2[idx]     = (float)((1.0 - acp) * sqrt(alpha) / (1.0 - ac));
            double pv     = beta * (1.0 - acp) / (1.0 - ac);
            if (pv < 1e-20) pv = 1e-20;
            g_sigma[idx]  = (float)exp(0.5 * log(pv));
        }
    }

    __shared__ float emb[TDIM];
    __shared__ float hid[HID];

    if (tid < TDIM) {
        int   j    = tid & 15;
        float freq = expf((float)j * (-logf(10000.0f) / 15.0f));
        float ang  = (float)i * freq;
        emb[tid]   = (tid < 16) ? sinf(ang) : cosf(ang);
    }
    __syncthreads();
    {
        float a = tb1[tid];
#pragma unroll
        for (int j = 0; j < TDIM; ++j)
            a = fmaf(emb[j], tW1[j * HID + tid], a);
        float sp = fmaxf(a, 0.0f) + log1pf(expf(-fabsf(a)));
        hid[tid] = a * tanhf(sp);
    }
    __syncthreads();
    if (tid < TDIM) {
        float a = tb2[tid];
#pragma unroll 8
        for (int h = 0; h < HID; ++h)
            a = fmaf(hid[h], tW2[h * TDIM + tid], a);
        g_temb[i * TDIM + tid] = a;
    }
}

// ---------------------------------------------------------------------------
// Dense layer 256-out, thread tile = 4 row-pairs x 4 cols, k-split 4.
// Thread = (ks, rh, cg): cols {2cg, 2cg+1, 2cg+128, 2cg+129},
// rows rp = 4rh..4rh+3.
// Per k: 2 LDS.128 (activations, broadcast) + 2 LDG.128 (dup weights,
// pack-free) + 16 FFMA2 -> ~84% FMA density, alu only addressing.
// Reduction: ks{0,1}->{out,red} store (rh halves disjoint rows),
// ks{2,3} add, then combine+mish spread pass.
// ---------------------------------------------------------------------------
template <int K, bool INPLACE>
__device__ __forceinline__ void dense44(
    const ull* __restrict__ in,
    const ull* __restrict__ Wd,
    const float* __restrict__ b,
    ull* __restrict__ out,
    ull* __restrict__ red,
    int cg, int rh, int ks, int tid)
{
    const int c0 = 2 * cg;           // pair A cols c0, c0+1
    const int c1 = c0 + 128;         // pair B cols c1, c1+1

    ull acc[4][4];                   // [rp][col: c0, c0+1, c1, c1+1]
    if (ks == 0) {
        const ull bA0 = pack2(b[c0], b[c0]);
        const ull bA1 = pack2(b[c0 + 1], b[c0 + 1]);
        const ull bB0 = pack2(b[c1], b[c1]);
        const ull bB1 = pack2(b[c1 + 1], b[c1 + 1]);
#pragma unroll
        for (int r = 0; r < 4; ++r) {
            acc[r][0] = bA0; acc[r][1] = bA1; acc[r][2] = bB0; acc[r][3] = bB1;
        }
    } else {
#pragma unroll
        for (int r = 0; r < 4; ++r)
#pragma unroll
            for (int j = 0; j < 4; ++j) acc[r][j] = 0;
    }

    const int kn = K / 4;            // 28 (K=112) or 64 (K=256); even
    const int kb = ks * kn;          // even
    const ull* ip  = in + (kb >> 1) * GSTR + 4 * rh;
    const ull* wpA = Wd + kb * HID + c0;

#pragma unroll 4
    for (int kk = 0; kk < kn; kk += 2) {
        // even k of the pair
        {
            const ulonglong2 a01 = *(const ulonglong2*)(ip + 0);
            const ulonglong2 a23 = *(const ulonglong2*)(ip + 2);
            const ulonglong2 wA = *(const ulonglong2*)(wpA);        // {w(c0)},{w(c0+1)}
            const ulonglong2 wB = *(const ulonglong2*)(wpA + 128);  // {w(c1)},{w(c1+1)}
            fma2(acc[0][0], a01.x, wA.x); fma2(acc[0][1], a01.x, wA.y);
            fma2(acc[0][2], a01.x, wB.x); fma2(acc[0][3], a01.x, wB.y);
            fma2(acc[1][0], a01.y, wA.x); fma2(acc[1][1], a01.y, wA.y);
            fma2(acc[1][2], a01.y, wB.x); fma2(acc[1][3], a01.y, wB.y);
            fma2(acc[2][0], a23.x, wA.x); fma2(acc[2][1], a23.x, wA.y);
            fma2(acc[2][2], a23.x, wB.x); fma2(acc[2][3], a23.x, wB.y);
            fma2(acc[3][0], a23.y, wA.x); fma2(acc[3][1], a23.y, wA.y);
            fma2(acc[3][2], a23.y, wB.x); fma2(acc[3][3], a23.y, wB.y);
        }
        // odd k of the pair
        {
            const ulonglong2 a01 = *(const ulonglong2*)(ip + 8);
            const ulonglong2 a23 = *(const ulonglong2*)(ip + 10);
            const ulonglong2 wA = *(const ulonglong2*)(wpA + HID);
            const ulonglong2 wB = *(const ulonglong2*)(wpA + HID + 128);
            fma2(acc[0][0], a01.x, wA.x); fma2(acc[0][1], a01.x, wA.y);
            fma2(acc[0][2], a01.x, wB.x); fma2(acc[0][3], a01.x, wB.y);
            fma2(acc[1][0], a01.y, wA.x); fma2(acc[1][1], a01.y, wA.y);
            fma2(acc[1][2], a01.y, wB.x); fma2(acc[1][3], a01.y, wB.y);
            fma2(acc[2][0], a23.x, wA.x); fma2(acc[2][1], a23.x, wA.y);
            fma2(acc[2][2], a23.x, wB.x); fma2(acc[2][3], a23.x, wB.y);
            fma2(acc[3][0], a23.y, wA.x); fma2(acc[3][1], a23.y, wA.y);
            fma2(acc[3][2], a23.y, wB.x); fma2(acc[3][3], a23.y, wB.y);
        }
        ip  += GSTR;
        wpA += 2 * HID;
    }

    if (INPLACE) __syncthreads();          // all reads of `in` complete

    // stage 1: ks0 -> out (bias folded), ks1 -> red; rh halves disjoint rows
    if (ks < 2) {
        ull* buf = (ks == 0 ? out : red);
        ull* oA = buf + cg * GSTR + 4 * rh;         // col pair A, group cg
        ull* oB = buf + (cg + 64) * GSTR + 4 * rh;  // col pair B, group cg+64
        *(ulonglong2*)(oA + 0)  = make_ulonglong2(acc[0][0], acc[1][0]);
        *(ulonglong2*)(oA + 2)  = make_ulonglong2(acc[2][0], acc[3][0]);
        *(ulonglong2*)(oA + 8)  = make_ulonglong2(acc[0][1], acc[1][1]);
        *(ulonglong2*)(oA + 10) = make_ulonglong2(acc[2][1], acc[3][1]);
        *(ulonglong2*)(oB + 0)  = make_ulonglong2(acc[0][2], acc[1][2]);
        *(ulonglong2*)(oB + 2)  = make_ulonglong2(acc[2][2], acc[3][2]);
        *(ulonglong2*)(oB + 8)  = make_ulonglong2(acc[0][3], acc[1][3]);
        *(ulonglong2*)(oB + 10) = make_ulonglong2(acc[2][3], acc[3][3]);
    }
    __syncthreads();

    // stage 2: ks2 += out, ks3 += red (disjoint buffers & rows)
    if (ks >= 2) {
        ull* buf = (ks == 2 ? out : red);
        ull* oA = buf + cg * GSTR + 4 * rh;
        ull* oB = buf + (cg + 64) * GSTR + 4 * rh;
#pragma unroll
        for (int cc = 0; cc < 2; ++cc) {
            ull* o = (cc == 0 ? oA : oB);
            const int j0 = cc * 2;
            ulonglong2 v0 = *(ulonglong2*)(o + 0);
            v0.x = add2(v0.x, acc[0][j0]); v0.y = add2(v0.y, acc[1][j0]);
            *(ulonglong2*)(o + 0) = v0;
            ulonglong2 v1 = *(ulonglong2*)(o + 2);
            v1.x = add2(v1.x, acc[2][j0]); v1.y = add2(v1.y, acc[3][j0]);
            *(ulonglong2*)(o + 2) = v1;
            ulonglong2 v2 = *(ulonglong2*)(o + 8);
            v2.x = add2(v2.x, acc[0][j0 + 1]); v2.y = add2(v2.y, acc[1][j0 + 1]);
            *(ulonglong2*)(o + 8) = v2;
            ulonglong2 v3 = *(ulonglong2*)(o + 10);
            v3.x = add2(v3.x, acc[2][j0 + 1]); v3.y = add2(v3.y, acc[3][j0 + 1]);
            *(ulonglong2*)(o + 10) = v3;
        }
    }
    __syncthreads();

    // combine + mish spread pass: data ull d = tid*4..+3, padded address
    {
        const int d0   = tid * 4;
        const int base = (d0 >> 4) * GSTR + (d0 & 15);
        ulonglong2* ph = (ulonglong2*)(out + base);
        const ulonglong2* pr = (const ulonglong2*)(red + base);
#pragma unroll
        for (int j = 0; j < 2; ++j) {
            ulonglong2 h = ph[j], r = pr[j];
            float l0, h0, l1, h1;
            unpack2(add2(h.x, r.x), l0, h0);
            unpack2(add2(h.y, r.y), l1, h1);
            ph[j] = make_ulonglong2(pack2(mishf(l0), mishf(h0)),
                                    pack2(mishf(l1), mishf(h1)));
        }
    }
    __syncthreads();
}

// ---------------------------------------------------------------------------
// Fused sampler: CTA owns 16 rows for all 100 steps. 512 threads.
// ---------------------------------------------------------------------------
__global__ void __launch_bounds__(NTHR, 1) sampler_kernel(
    const float* __restrict__ state,
    const float* __restrict__ x_init,
    const float* __restrict__ noise,
    const float* __restrict__ b1, const float* __restrict__ b2,
    const float* __restrict__ b3, const float* __restrict__ b4,
    float* __restrict__ out)
{
    __shared__ __align__(16) ull a0[(CAT / 2) * GSTR];   //  7.9 KB layer-1 input
    __shared__ __align__(16) ull hbuf[(HID / 2) * GSTR]; // 18.0 KB layers 1-3
    __shared__ __align__(16) ull red[(HID / 2) * GSTR];  // 18.0 KB partials
    // L4 partials (512 ull) alias `red` — dead after the L3 combine pass.
    ull* red4 = red;

    const int tid  = threadIdx.x;
    const int cg   = tid & 63;          // col group 0..63
    const int rh   = (tid >> 6) & 1;    // row half 0..1
    const int ks   = tid >> 7;          // k-quarter 0..3
    const int row0 = blockIdx.x * RPC;

    // ---- one-time fills (padded, row-pair packed) ----
    if (tid < 128) {                 // x: 16 feats x 8 rp
        int f = tid >> 3, rp = tid & 7;
        a0[lay(f, rp)] = pack2(x_init[(row0 + 2 * rp)     * ADIM + f],
                               x_init[(row0 + 2 * rp + 1) * ADIM + f]);
    }
    {                                // state: 64 feats x 8 rp = 512
        int f = tid >> 3, rp = tid & 7;
        a0[lay(ADIM + TDIM + f, rp)] =
            pack2(state[(row0 + 2 * rp)     * SDIM + f],
                  state[(row0 + 2 * rp + 1) * SDIM + f]);
    }

    for (int s = 0; s < TSTEPS; ++s) {
        const int i = TSTEPS - 1 - s;

        if (tid < 256) {             // temb: 32 feats x 8 rp (row-invariant)
            int f = tid >> 3, rp = tid & 7;
            float t = g_temb[i * TDIM + f];
            a0[lay(ADIM + f, rp)] = pack2(t, t);
        }
        __syncthreads();

        dense44<CAT, false>(a0,   g_W1d, b1, hbuf, red, cg, rh, ks, tid);
        dense44<HID, true >(hbuf, g_W2d, b2, hbuf, red, cg, rh, ks, tid);
        dense44<HID, true >(hbuf, g_W3d, b3, hbuf, red, cg, rh, ks, tid);

        // ---- layer 4 (256 -> 16): thread = (k-quarter, rp, c), dup table ----
        {
            const int c  = tid & 15;
            const int rp = (tid >> 4) & 7;
            const int k4 = tid >> 7;        // 0..3
            ull acc = 0;
            const int kb = k4 * 64;
#pragma unroll 8
            for (int kk = 0; kk < 64; ++kk) {
                const int k = kb + kk;
                fma2(acc, hbuf[lay(k, rp)], g_W4d[k * ADIM + c]);
            }
            red4[(rp * ADIM + c) * 4 + k4] = acc;
        }
        __syncthreads();

        // ---- reduce + posterior (128 threads: rp, c) ----
        if (tid < 128) {
            const int rp = tid >> 4, c = tid & 15;
            const ull* r = red4 + (rp * ADIM + c) * 4;
            ull e = add2(add2(r[0], r[1]), add2(r[2], r[3]));
            float e0, e1; unpack2(e, e0, e1);
            const float bb = b4[c];
            e0 += bb; e1 += bb;

            float x0, x1; unpack2(a0[lay(c, rp)], x0, x1);
            const float sr = g_srac[i], srm = g_sracm1[i];
            const float c1 = g_c1[i],   c2  = g_c2[i];

            float r0 = fminf(fmaxf(sr * x0 - srm * e0, -1.0f), 1.0f);
            float r1 = fminf(fmaxf(sr * x1 - srm * e1, -1.0f), 1.0f);
            float m0 = c1 * r0 + c2 * x0;
            float m1 = c1 * r1 + c2 * x1;

            if (i > 0) {
                const float sg = g_sigma[i];
                const float* nz = noise + (size_t)s * BATCH * ADIM;
                float n0 = nz[(row0 + 2 * rp)     * ADIM + c];
                float n1 = nz[(row0 + 2 * rp + 1) * ADIM + c];
                a0[lay(c, rp)] = pack2(fmaf(sg, n0, m0), fmaf(sg, n1, m1));
            } else {
                out[(row0 + 2 * rp)     * ADIM + c] = fminf(fmaxf(m0, -1.0f), 1.0f);
                out[(row0 + 2 * rp + 1) * ADIM + c] = fminf(fmaxf(m1, -1.0f), 1.0f);
            }
        }
        __syncthreads();
    }
}

// ---------------------------------------------------------------------------
// kernel_launch
// ---------------------------------------------------------------------------
extern "C" void kernel_launch(void* const* d_in, const int* in_sizes, int n_in,
                              void* d_out, int out_size)
{
    const float* state  = (const float*)d_in[0];
    const float* x_init = (const float*)d_in[1];
    const float* noise  = (const float*)d_in[2];
    const float* tW1    = (const float*)d_in[3];
    const float* tb1    = (const float*)d_in[4];
    const float* tW2    = (const float*)d_in[5];
    const float* tb2    = (const float*)d_in[6];
    const float* W1     = (const float*)d_in[7];
    const float* b1     = (const float*)d_in[8];
    const float* W2     = (const float*)d_in[9];
    const float* b2     = (const float*)d_in[10];
    const float* W3     = (const float*)d_in[11];
    const float* b3     = (const float*)d_in[12];
    const float* W4     = (const float*)d_in[13];
    const float* b4     = (const float*)d_in[14];
    float* out          = (float*)d_out;

    setup_dup_kernel<<<(HID * HID + 511) / 512, 512>>>(W1, W2, W3, W4);
    prolog_kernel<<<TSTEPS, 256>>>(tW1, tb1, tW2, tb2);
    sampler_kernel<<<NCTA, NTHR>>>(state, x_init, noise,
                                   b1, b2, b3, b4, out);
}

// round 15
// speedup vs baseline: 1.1051x; 1.1051x over previous
#include <cuda_runtime.h>
#include <cuda_bf16.h>
#include <math.h>
#include <stdint.h>

// ---------------------------------------------------------------------------
// Problem constants
// ---------------------------------------------------------------------------
#define BATCH     2048
#define SDIM      64
#define ADIM      16
#define HID       256
#define TDIM      32
#define TSTEPS    100
#define CAT       112            // ADIM + TDIM + SDIM
#define RPC       16             // rows per CTA
#define NRP       8              // row-pairs per CTA
#define NCTA      (BATCH / RPC)  // 128
#define NTHR      512            // 128 col-pair threads x 4 k-quarters
#define GSTR      18             // ull per 2-col group (16 data + 2 pad)

#define NCHUNK_STEP 11           // W1:2  W2:4  W3:4  W4:1
#define JMAX        (NCHUNK_STEP * TSTEPS)
#define WBUF_F      16384        // floats per staging buffer (64 KB)

typedef unsigned long long ull;

// dynamic smem layout (ull units):
//   a0   [0      .. 1008)   layer-1 input  (56 groups * 18)
//   hbuf [1008   .. 3312)   layers 1-3 activations (128 groups * 18)
//   red  [3312   .. 5616)   reduction partials
//   ws   [5616   .. 22000)  weight staging: 2 x 16384 floats (2 x 64 KB)
//   mbar [22000  .. 22002)  2 mbarriers
#define OFF_A0    0
#define OFF_HBUF  1008
#define OFF_RED   3312
#define OFF_WS    5616
#define OFF_MBAR  22000
#define SMEM_BYTES ((OFF_MBAR + 4) * 8)   // 176032 B

// padded layout: value (col c, row-pair rp) at (c>>1)*GSTR + (c&1)*8 + rp
__device__ __forceinline__ int lay(int c, int rp) {
    return (c >> 1) * GSTR + (c & 1) * 8 + rp;
}

// ---------------------------------------------------------------------------
// Precomputed tables
// ---------------------------------------------------------------------------
__device__ float g_temb[TSTEPS * TDIM];
__device__ float g_srac[TSTEPS];
__device__ float g_sracm1[TSTEPS];
__device__ float g_c1[TSTEPS];
__device__ float g_c2[TSTEPS];
__device__ float g_sigma[TSTEPS];

// ---------------------------------------------------------------------------
// f32x2 helpers
// ---------------------------------------------------------------------------
__device__ __forceinline__ ull pack2(float lo, float hi) {
    ull r; asm("mov.b64 %0, {%1, %2};" : "=l"(r) : "f"(lo), "f"(hi)); return r;
}
__device__ __forceinline__ void unpack2(ull v, float& lo, float& hi) {
    asm("mov.b64 {%0, %1}, %2;" : "=f"(lo), "=f"(hi) : "l"(v));
}
__device__ __forceinline__ void fma2(ull& d, ull a, ull b) {
    asm("fma.rn.f32x2 %0, %1, %2, %0;" : "+l"(d) : "l"(a), "l"(b));
}
__device__ __forceinline__ ull add2(ull a, ull b) {
    ull r; asm("add.rn.f32x2 %0, %1, %2;" : "=l"(r) : "l"(a), "l"(b)); return r;
}

// ---------------------------------------------------------------------------
// Fast exact-algebra mish: tanh(softplus(x)) = v/(v+2), v = u^2+2u, u = e^x
// ---------------------------------------------------------------------------
__device__ __forceinline__ float mishf(float x) {
    const float LOG2E = 1.4426950408889634f;
    float xc = fminf(x, 40.0f);
    float u;
    asm("ex2.approx.f32 %0, %1;" : "=f"(u) : "f"(xc * LOG2E));
    float v = fmaf(u, u, u + u);
    float r;
    asm("rcp.approx.f32 %0, %1;" : "=f"(r) : "f"(v + 2.0f));
    return x * v * r;
}

// ---------------------------------------------------------------------------
// mbarrier helpers
// ---------------------------------------------------------------------------
__device__ __forceinline__ uint32_t smem_u32(const void* p) {
    uint32_t a;
    asm("{ .reg .u64 t; cvta.to.shared.u64 t, %1; cvt.u32.u64 %0, t; }"
        : "=r"(a) : "l"(p));
    return a;
}
__device__ __forceinline__ void mbar_init(uint32_t mb, uint32_t cnt) {
    asm volatile("mbarrier.init.shared.b64 [%0], %1;" :: "r"(mb), "r"(cnt) : "memory");
}
__device__ __forceinline__ void mbar_expect_tx(uint32_t mb, uint32_t bytes) {
    asm volatile("mbarrier.arrive.expect_tx.shared.b64 _, [%0], %1;"
                 :: "r"(mb), "r"(bytes) : "memory");
}
__device__ __forceinline__ void mbar_wait(uint32_t mb, uint32_t phase) {
    asm volatile(
        "{\n\t.reg .pred P;\n\t"
        "WL_%=:\n\t"
        "mbarrier.try_wait.parity.acquire.cta.shared::cta.b64 P, [%0], %1, 0x989680;\n\t"
        "@!P bra WL_%=;\n\t"
        "}" :: "r"(mb), "r"(phase) : "memory");
}

// issue staged weight chunk j (thread 0 only). Flat cyclic schedule:
//  m = j mod 11: 0-1 -> W1 (64k, 48k rows), 2-5 -> W2, 6-9 -> W3, 10 -> W4.
__device__ __forceinline__ void issue_chunk(
    int j,
    const float* __restrict__ W1, const float* __restrict__ W2,
    const float* __restrict__ W3, const float* __restrict__ W4,
    uint32_t ws_addr, uint32_t mb_addr)
{
    const int m = j % NCHUNK_STEP;
    const float* src;
    uint32_t bytes;
    switch (m) {
        case 0:  src = W1;         bytes = 65536; break;
        case 1:  src = W1 + 16384; bytes = 49152; break;   // 48 rows
        case 2:  src = W2;         bytes = 65536; break;
        case 3:  src = W2 + 16384; bytes = 65536; break;
        case 4:  src = W2 + 32768; bytes = 65536; break;
        case 5:  src = W2 + 49152; bytes = 65536; break;
        case 6:  src = W3;         bytes = 65536; break;
        case 7:  src = W3 + 16384; bytes = 65536; break;
        case 8:  src = W3 + 32768; bytes = 65536; break;
        case 9:  src = W3 + 49152; bytes = 65536; break;
        default: src = W4;         bytes = 16384; break;
    }
    const uint32_t dst = ws_addr + (uint32_t)(j & 1) * (WBUF_F * 4u);
    const uint32_t mb  = mb_addr + (uint32_t)(j & 1) * 8u;
    mbar_expect_tx(mb, bytes);
    asm volatile(
        "cp.async.bulk.shared::cluster.global.mbarrier::complete_tx::bytes "
        "[%0], [%1], %2, [%3];"
        :: "r"(dst), "l"(src), "r"(bytes), "r"(mb) : "memory");
}

// ---------------------------------------------------------------------------
// Prolog: VP schedule in f64 + per-timestep time-MLP (batch-invariant).
// ---------------------------------------------------------------------------
__global__ void __launch_bounds__(256) prolog_kernel(
    const float* __restrict__ tW1, const float* __restrict__ tb1,
    const float* __restrict__ tW2, const float* __restrict__ tb2)
{
    const int tid = threadIdx.x;
    const int i   = blockIdx.x;

    if (i == 0 && tid == 0) {
        const double T = (double)TSTEPS, bmax = 10.0, bmin = 0.1;
        double ac = 1.0;
        for (int idx = 0; idx < TSTEPS; ++idx) {
            double t      = (double)(idx + 1);
            double alpha  = exp(-bmin / T - 0.5 * (bmax - bmin) * (2.0 * t - 1.0) / (T * T));
            double beta   = 1.0 - alpha;
            double acp    = ac;
            ac            = ac * alpha;
            g_srac[idx]   = (float)sqrt(1.0 / ac);
            g_sracm1[idx] = (float)sqrt(1.0 / ac - 1.0);
            g_c1[idx]     = (float)(beta * sqrt(acp) / (1.0 - ac));
            g_c2[idx]     = (float)((1.0 - acp) * sqrt(alpha) / (1.0 - ac));
            double pv     = beta * (1.0 - acp) / (1.0 - ac);
            if (pv < 1e-20) pv = 1e-20;
            g_sigma[idx]  = (float)exp(0.5 * log(pv));
        }
    }

    __shared__ float emb[TDIM];
    __shared__ float hid[HID];

    if (tid < TDIM) {
        int   jj   = tid & 15;
        float freq = expf((float)jj * (-logf(10000.0f) / 15.0f));
        float ang  = (float)i * freq;
        emb[tid]   = (tid < 16) ? sinf(ang) : cosf(ang);
    }
    __syncthreads();
    {
        float a = tb1[tid];
#pragma unroll
        for (int jj = 0; jj < TDIM; ++jj)
            a = fmaf(emb[jj], tW1[jj * HID + tid], a);
        float sp = fmaxf(a, 0.0f) + log1pf(expf(-fabsf(a)));
        hid[tid] = a * tanhf(sp);
    }
    __syncthreads();
    if (tid < TDIM) {
        float a = tb2[tid];
#pragma unroll 8
        for (int h = 0; h < HID; ++h)
            a = fmaf(hid[h], tW2[h * TDIM + tid], a);
        g_temb[i * TDIM + tid] = a;
    }
}

// ---------------------------------------------------------------------------
// Dense layer 256-out from STAGED smem weights. Tile = 8 row-pairs x 2 cols,
// k-split 4 remapped chunk-local (each quarter takes nq = chunk_k/4 rows of
// every chunk so all 512 threads work on every chunk). Accumulators carry
// across chunks. Per k: 4 LDS.128 (acts, broadcast) + 1 LDS.64 (weights,
// 29-cyc smem, conflict-free) + 2 packs + 16 FFMA2 -> no LDG in the loop.
// After last chunk: R11 staged reduction + combine+mish spread pass.
// ---------------------------------------------------------------------------
__device__ __forceinline__ void dense_staged(
    const ull* __restrict__ in,
    const float* __restrict__ ws, uint32_t ws_addr, uint32_t mb_addr,
    const float* __restrict__ b,
    ull* __restrict__ out, ull* __restrict__ red,
    int cg, int ks, int tid, int& j,
    int nch, const int* kbs, const int* kns,
    const float* __restrict__ W1, const float* __restrict__ W2,
    const float* __restrict__ W3, const float* __restrict__ W4)
{
    const int c0 = 2 * cg;
    ull acc[NRP][2];
    if (ks == 0) {
        const ull b0 = pack2(b[c0], b[c0]);
        const ull b1 = pack2(b[c0 + 1], b[c0 + 1]);
#pragma unroll
        for (int rp = 0; rp < NRP; ++rp) { acc[rp][0] = b0; acc[rp][1] = b1; }
    } else {
#pragma unroll
        for (int rp = 0; rp < NRP; ++rp) { acc[rp][0] = 0; acc[rp][1] = 0; }
    }

    for (int ci = 0; ci < nch; ++ci) {
        mbar_wait(mb_addr + (uint32_t)(j & 1) * 8u, (uint32_t)((j >> 1) & 1));
        const float* wb = ws + (j & 1) * WBUF_F;
        const int nq = kns[ci] >> 2;            // 16 or 12 (even)
        const int kg = kbs[ci] + ks * nq;       // even
        const ull*   ip = in + (kg >> 1) * GSTR;
        const float* wp = wb + (ks * nq) * HID + c0;

#pragma unroll 4
        for (int t = 0; t < nq; t += 2) {
            // even k
            {
                const ulonglong2 a01 = *(const ulonglong2*)(ip + 0);
                const ulonglong2 a23 = *(const ulonglong2*)(ip + 2);
                const ulonglong2 a45 = *(const ulonglong2*)(ip + 4);
                const ulonglong2 a67 = *(const ulonglong2*)(ip + 6);
                const float2 wf = *(const float2*)wp;
                const ull w0 = pack2(wf.x, wf.x);
                const ull w1 = pack2(wf.y, wf.y);
                fma2(acc[0][0], a01.x, w0);  fma2(acc[0][1], a01.x, w1);
                fma2(acc[1][0], a01.y, w0);  fma2(acc[1][1], a01.y, w1);
                fma2(acc[2][0], a23.x, w0);  fma2(acc[2][1], a23.x, w1);
                fma2(acc[3][0], a23.y, w0);  fma2(acc[3][1], a23.y, w1);
                fma2(acc[4][0], a45.x, w0);  fma2(acc[4][1], a45.x, w1);
                fma2(acc[5][0], a45.y, w0);  fma2(acc[5][1], a45.y, w1);
                fma2(acc[6][0], a67.x, w0);  fma2(acc[6][1], a67.x, w1);
                fma2(acc[7][0], a67.y, w0);  fma2(acc[7][1], a67.y, w1);
            }
            // odd k
            {
                const ulonglong2 a01 = *(const ulonglong2*)(ip + 8);
                const ulonglong2 a23 = *(const ulonglong2*)(ip + 10);
                const ulonglong2 a45 = *(const ulonglong2*)(ip + 12);
                const ulonglong2 a67 = *(const ulonglong2*)(ip + 14);
                const float2 wf = *(const float2*)(wp + HID);
                const ull w0 = pack2(wf.x, wf.x);
                const ull w1 = pack2(wf.y, wf.y);
                fma2(acc[0][0], a01.x, w0);  fma2(acc[0][1], a01.x, w1);
                fma2(acc[1][0], a01.y, w0);  fma2(acc[1][1], a01.y, w1);
                fma2(acc[2][0], a23.x, w0);  fma2(acc[2][1], a23.x, w1);
                fma2(acc[3][0], a23.y, w0);  fma2(acc[3][1], a23.y, w1);
                fma2(acc[4][0], a45.x, w0);  fma2(acc[4][1], a45.x, w1);
                fma2(acc[5][0], a45.y, w0);  fma2(acc[5][1], a45.y, w1);
                fma2(acc[6][0], a67.x, w0);  fma2(acc[6][1], a67.x, w1);
                fma2(acc[7][0], a67.y, w0);  fma2(acc[7][1], a67.y, w1);
            }
            ip += GSTR;
            wp += 2 * HID;
        }

        __syncthreads();                       // all consumed buf (j&1)
        if (tid == 0 && (j + 2) < JMAX)
            issue_chunk(j + 2, W1, W2, W3, W4, ws_addr, mb_addr);
        ++j;
    }

    // stage 1: ks0 -> out (bias folded), ks1 -> red
    if (ks < 2) {
        ull* o = (ks == 0 ? out : red) + cg * GSTR;
#pragma unroll
        for (int cc = 0; cc < 2; ++cc)
#pragma unroll
            for (int rp = 0; rp < NRP; rp += 2)
                *(ulonglong2*)(o + cc * 8 + rp) =
                    make_ulonglong2(acc[rp][cc], acc[rp + 1][cc]);
    }
    __syncthreads();

    // stage 2: ks2 += out, ks3 += red
    if (ks >= 2) {
        ull* o = (ks == 2 ? out : red) + cg * GSTR;
#pragma unroll
        for (int cc = 0; cc < 2; ++cc)
#pragma unroll
            for (int rp = 0; rp < NRP; rp += 2) {
                ulonglong2 v = *(ulonglong2*)(o + cc * 8 + rp);
                v.x = add2(v.x, acc[rp][cc]);
                v.y = add2(v.y, acc[rp + 1][cc]);
                *(ulonglong2*)(o + cc * 8 + rp) = v;
            }
    }
    __syncthreads();

    // combine + mish spread pass
    {
        const int d0   = tid * 4;
        const int base = (d0 >> 4) * GSTR + (d0 & 15);
        ulonglong2* ph = (ulonglong2*)(out + base);
        const ulonglong2* pr = (const ulonglong2*)(red + base);
#pragma unroll
        for (int jj = 0; jj < 2; ++jj) {
            ulonglong2 h = ph[jj], r = pr[jj];
            float l0, h0, l1, h1;
            unpack2(add2(h.x, r.x), l0, h0);
            unpack2(add2(h.y, r.y), l1, h1);
            ph[jj] = make_ulonglong2(pack2(mishf(l0), mishf(h0)),
                                     pack2(mishf(l1), mishf(h1)));
        }
    }
    __syncthreads();
}

// ---------------------------------------------------------------------------
// Fused sampler: CTA owns 16 rows for all 100 steps. 512 threads.
// Weights stream through a 2 x 64 KB smem double buffer via cp.async.bulk.
// ---------------------------------------------------------------------------
__global__ void __launch_bounds__(NTHR, 1) sampler_kernel(
    const float* __restrict__ state,
    const float* __restrict__ x_init,
    const float* __restrict__ noise,
    const float* __restrict__ W1, const float* __restrict__ b1,
    const float* __restrict__ W2, const float* __restrict__ b2,
    const float* __restrict__ W3, const float* __restrict__ b3,
    const float* __restrict__ W4, const float* __restrict__ b4,
    float* __restrict__ out)
{
    extern __shared__ __align__(16) ull dsm[];
    ull*   a0   = dsm + OFF_A0;
    ull*   hbuf = dsm + OFF_HBUF;
    ull*   red  = dsm + OFF_RED;
    float* ws   = (float*)(dsm + OFF_WS);
    ull*   red4 = red;                       // L4 partials alias red

    const uint32_t ws_addr = smem_u32(ws);
    const uint32_t mb_addr = smem_u32(dsm + OFF_MBAR);

    const int tid  = threadIdx.x;
    const int cg   = tid & 127;      // col-pair 0..127
    const int ks   = tid >> 7;       // k-quarter 0..3
    const int row0 = blockIdx.x * RPC;

    // ---- mbarrier init + initial chunk issues ----
    if (tid == 0) {
        mbar_init(mb_addr, 1);
        mbar_init(mb_addr + 8, 1);
        asm volatile("fence.proxy.async.shared::cta;" ::: "memory");
    }

    // ---- one-time fills (padded, row-pair packed) ----
    if (tid < 128) {                 // x: 16 feats x 8 rp
        int f = tid >> 3, rp = tid & 7;
        a0[lay(f, rp)] = pack2(x_init[(row0 + 2 * rp)     * ADIM + f],
                               x_init[(row0 + 2 * rp + 1) * ADIM + f]);
    }
    {                                // state: 64 feats x 8 rp = 512
        int f = tid >> 3, rp = tid & 7;
        a0[lay(ADIM + TDIM + f, rp)] =
            pack2(state[(row0 + 2 * rp)     * SDIM + f],
                  state[(row0 + 2 * rp + 1) * SDIM + f]);
    }
    __syncthreads();                 // mbar init visible to all
    if (tid == 0) {
        issue_chunk(0, W1, W2, W3, W4, ws_addr, mb_addr);
        issue_chunk(1, W1, W2, W3, W4, ws_addr, mb_addr);
    }

    int j = 0;                       // global chunk counter (all threads)

    const int kbsL1[2] = {0, 64};
    const int knsL1[2] = {64, 48};
    const int kbsH[4]  = {0, 64, 128, 192};
    const int knsH[4]  = {64, 64, 64, 64};

    for (int s = 0; s < TSTEPS; ++s) {
        const int i = TSTEPS - 1 - s;

        if (tid < 256) {             // temb: 32 feats x 8 rp (row-invariant)
            int f = tid >> 3, rp = tid & 7;
            float t = g_temb[i * TDIM + f];
            a0[lay(ADIM + f, rp)] = pack2(t, t);
        }
        __syncthreads();

        dense_staged(a0,   ws, ws_addr, mb_addr, b1, hbuf, red,
                     cg, ks, tid, j, 2, kbsL1, knsL1, W1, W2, W3, W4);
        dense_staged(hbuf, ws, ws_addr, mb_addr, b2, hbuf, red,
                     cg, ks, tid, j, 4, kbsH,  knsH,  W1, W2, W3, W4);
        dense_staged(hbuf, ws, ws_addr, mb_addr, b3, hbuf, red,
                     cg, ks, tid, j, 4, kbsH,  knsH,  W1, W2, W3, W4);

        // ---- layer 4 (256 -> 16) from staged W4 chunk ----
        mbar_wait(mb_addr + (uint32_t)(j & 1) * 8u, (uint32_t)((j >> 1) & 1));
        {
            const float* w4b = ws + (j & 1) * WBUF_F;
            const int c  = tid & 15;
            const int rp = (tid >> 4) & 7;
            const int k4 = tid >> 7;        // 0..3
            ull acc = 0;
            const int kb = k4 * 64;
#pragma unroll 8
            for (int kk = 0; kk < 64; ++kk) {
                const int k = kb + kk;
                const float w = w4b[k * ADIM + c];
                fma2(acc, hbuf[lay(k, rp)], pack2(w, w));
            }
            red4[(rp * ADIM + c) * 4 + k4] = acc;
        }
        __syncthreads();
        if (tid == 0 && (j + 2) < JMAX)
            issue_chunk(j + 2, W1, W2, W3, W4, ws_addr, mb_addr);
        ++j;

        // ---- reduce + posterior (128 threads: rp, c) ----
        if (tid < 128) {
            const int rp = tid >> 4, c = tid & 15;
            const ull* r = red4 + (rp * ADIM + c) * 4;
            ull e = add2(add2(r[0], r[1]), add2(r[2], r[3]));
            float e0, e1; unpack2(e, e0, e1);
            const float bb = b4[c];
            e0 += bb; e1 += bb;

            float x0, x1; unpack2(a0[lay(c, rp)], x0, x1);
            const float sr = g_srac[i], srm = g_sracm1[i];
            const float c1 = g_c1[i],   c2  = g_c2[i];

            float r0 = fminf(fmaxf(sr * x0 - srm * e0, -1.0f), 1.0f);
            float r1 = fminf(fmaxf(sr * x1 - srm * e1, -1.0f), 1.0f);
            float m0 = c1 * r0 + c2 * x0;
            float m1 = c1 * r1 + c2 * x1;

            if (i > 0) {
                const float sg = g_sigma[i];
                const float* nz = noise + (size_t)s * BATCH * ADIM;
                float n0 = nz[(row0 + 2 * rp)     * ADIM + c];
                float n1 = nz[(row0 + 2 * rp + 1) * ADIM + c];
                a0[lay(c, rp)] = pack2(fmaf(sg, n0, m0), fmaf(sg, n1, m1));
            } else {
                out[(row0 + 2 * rp)     * ADIM + c] = fminf(fmaxf(m0, -1.0f), 1.0f);
                out[(row0 + 2 * rp + 1) * ADIM + c] = fminf(fmaxf(m1, -1.0f), 1.0f);
            }
        }
        __syncthreads();
    }
}

// ---------------------------------------------------------------------------
// kernel_launch
// ---------------------------------------------------------------------------
extern "C" void kernel_launch(void* const* d_in, const int* in_sizes, int n_in,
                              void* d_out, int out_size)
{
    const float* state  = (const float*)d_in[0];
    const float* x_init = (const float*)d_in[1];
    const float* noise  = (const float*)d_in[2];
    const float* tW1    = (const float*)d_in[3];
    const float* tb1    = (const float*)d_in[4];
    const float* tW2    = (const float*)d_in[5];
    const float* tb2    = (const float*)d_in[6];
    const float* W1     = (const float*)d_in[7];
    const float* b1     = (const float*)d_in[8];
    const float* W2     = (const float*)d_in[9];
    const float* b2     = (const float*)d_in[10];
    const float* W3     = (const float*)d_in[11];
    const float* b3     = (const float*)d_in[12];
    const float* W4     = (const float*)d_in[13];
    const float* b4     = (const float*)d_in[14];
    float* out          = (float*)d_out;

    // device-function attribute set; idempotent, not a stream operation
    cudaFuncSetAttribute(sampler_kernel,
                         cudaFuncAttributeMaxDynamicSharedMemorySize,
                         SMEM_BYTES);

    prolog_kernel<<<TSTEPS, 256>>>(tW1, tb1, tW2, tb2);
    sampler_kernel<<<NCTA, NTHR, SMEM_BYTES>>>(state, x_init, noise,
                                               W1, b1, W2, b2, W3, b3, W4, b4,
                                               out);
}